// round 11
// baseline (speedup 1.0000x reference)
#include <cuda_runtime.h>
#include <cstdint>

#define N_VEH 16
#define N_PED 16
#define NTOK  32
#define DVEH  40
#define DPED  24
#define EDIM  128
#define NHEAD 4
#define OBSD  1056   // 16*40 + 16*24 + 32

// Quad-packed tf32 weights: g_wtp4[l][kp][n][tig] =
//   (w[kp*16+tig][n], w[kp*16+tig+4][n], w[kp*16+tig+8][n], w[kp*16+tig+12][n])
__device__ uint4 g_wtp4[2][8][EDIM][4];
// Quad-packed folded-alpha weights: [l][kp][j][tig], j: 0-3 src head, 4-7 dst head.
__device__ uint4 g_wtAp4[2][8][8][4];
// Quad-packed embedding weights (rows >= D zero-filled).
__device__ uint4 g_wvp4[3][EDIM][4];
__device__ uint4 g_wpp4[2][EDIM][4];

__device__ __forceinline__ uint32_t f2tf32(float f) {
    uint32_t r;
    asm("cvt.rna.tf32.f32 %0, %1;" : "=r"(r) : "f"(f));
    return r;
}
__device__ __forceinline__ float tf32r(float f) {
    return __uint_as_float(f2tf32(f));
}

__device__ __forceinline__ void mma_tf32(float* c, const uint32_t* a,
                                         uint32_t b0, uint32_t b1) {
    asm("mma.sync.aligned.m16n8k8.row.col.f32.tf32.tf32.f32 "
        "{%0,%1,%2,%3}, {%4,%5,%6,%7}, {%8,%9}, {%0,%1,%2,%3};"
        : "+f"(c[0]), "+f"(c[1]), "+f"(c[2]), "+f"(c[3])
        : "r"(a[0]), "r"(a[1]), "r"(a[2]), "r"(a[3]), "r"(b0), "r"(b1));
}

// ---- fragment-paired SMEM layouts ----
// PL (x matrices): pair (r, c) with (r, c+4) adjacent; bank-XOR on pair index.
__device__ __forceinline__ int plOff(int r, int c) {
    int p   = ((c >> 3) << 2) | (c & 3);     // pair index 0..63
    int hi  = (c >> 2) & 1;
    int sig = ((r & 3) << 2) | ((r >> 2) & 3);
    return (r << 7) + (((p ^ sig)) << 1) + hi;
}
// QL (h matrices): pair (r, c) with (r+4, c) adjacent.
__device__ __forceinline__ int qlOff(int r, int c) {
    int rr = ((r >> 3) << 2) | (r & 3);      // row-pair index 0..15
    int hi = (r >> 2) & 1;
    return (rr << 8) + ((c ^ ((rr & 3) << 2)) << 1) + hi;
}

// Fused prep: quad-pack main, alpha, and embedding weights as tf32.
__global__ void prep_kernel(const float* __restrict__ w0,
                            const float* __restrict__ as0, const float* __restrict__ ad0,
                            const float* __restrict__ w1,
                            const float* __restrict__ as1, const float* __restrict__ ad1,
                            const float* __restrict__ Wv, const float* __restrict__ Wp) {
    int idx = blockIdx.x * blockDim.x + threadIdx.x;
    if (idx < 8192) {                        // main: 2*8*128*4
        int l   = idx >> 12;
        int rem = idx & 4095;
        int kp  = rem >> 9;
        int n   = (rem >> 2) & 127;
        int tig = rem & 3;
        const float* w = l ? w1 : w0;
        int k = kp * 16 + tig;
        g_wtp4[l][kp][n][tig] = make_uint4(
            f2tf32(w[k * EDIM + n]),        f2tf32(w[(k + 4) * EDIM + n]),
            f2tf32(w[(k + 8) * EDIM + n]),  f2tf32(w[(k + 12) * EDIM + n]));
    } else if (idx < 8192 + 512) {           // alpha: 2*8*8*4
        int i2  = idx - 8192;
        int l   = i2 >> 8;
        int kp  = (i2 >> 5) & 7;
        int j   = (i2 >> 2) & 7;
        int tig = i2 & 3;
        const float* w = l ? w1 : w0;
        int h = j & 3;
        const float* a = (j < 4) ? (l ? as1 : as0) : (l ? ad1 : ad0);
        float s0 = 0.f, s1 = 0.f, s2 = 0.f, s3 = 0.f;
#pragma unroll
        for (int d = 0; d < 32; ++d) {
            float av = a[h * 32 + d];
            int base = (kp * 16 + tig) * EDIM + h * 32 + d;
            s0 = fmaf(w[base],             av, s0);
            s1 = fmaf(w[base + 4 * EDIM],  av, s1);
            s2 = fmaf(w[base + 8 * EDIM],  av, s2);
            s3 = fmaf(w[base + 12 * EDIM], av, s3);
        }
        g_wtAp4[l][kp][j][tig] = make_uint4(f2tf32(s0), f2tf32(s1),
                                            f2tf32(s2), f2tf32(s3));
    } else if (idx < 8192 + 512 + 1536) {    // Wv: 3*128*4
        int i2  = idx - 8704;
        int kp  = i2 >> 9;
        int n   = (i2 >> 2) & 127;
        int tig = i2 & 3;
        uint32_t v[4];
#pragma unroll
        for (int q = 0; q < 4; ++q) {
            int k = kp * 16 + tig + 4 * q;
            v[q] = (k < DVEH) ? f2tf32(Wv[k * EDIM + n]) : 0u;
        }
        g_wvp4[kp][n][tig] = make_uint4(v[0], v[1], v[2], v[3]);
    } else if (idx < 8192 + 512 + 1536 + 1024) {   // Wp: 2*128*4
        int i2  = idx - 10240;
        int kp  = i2 >> 9;
        int n   = (i2 >> 2) & 127;
        int tig = i2 & 3;
        uint32_t v[4];
#pragma unroll
        for (int q = 0; q < 4; ++q) {
            int k = kp * 16 + tig + 4 * q;
            v[q] = (k < DPED) ? f2tf32(Wp[k * EDIM + n]) : 0u;
        }
        g_wpp4[kp][n][tig] = make_uint4(v[0], v[1], v[2], v[3]);
    }
}

__global__ __launch_bounds__(128, 6) void gnn_kernel(
    const float* __restrict__ obs,
    const float* __restrict__ bv, const float* __restrict__ bp,
    float* __restrict__ out)
{
    const int b    = blockIdx.x;
    const int t    = threadIdx.x;
    const int lane = t & 31;
    const int warp = t >> 5;
    const int gID  = lane >> 2;
    const int tig  = lane & 3;
    const int sigr = ((gID & 3) << 2) | (gID >> 2);

    extern __shared__ float smem[];
    float* bufP = smem;
    float* bufQ = smem + 4096;

    __shared__ float s_as[NTOK][NHEAD];
    __shared__ float s_adt[NHEAD][NTOK];
    __shared__ float s_bias[NTOK];
    __shared__ float s_alive[NTOK];
    __shared__ float s_inv;

    // ---- stage observation row into bufQ ----
    {
        const float4* src = (const float4*)(obs + (size_t)b * OBSD);
        float4* dst = (float4*)bufQ;
        for (int i = t; i < OBSD / 4; i += 128) dst[i] = src[i];
    }
    __syncthreads();
    const float* s_obs = bufQ;

    // ---- alive mask (warp 0) ----
    if (warp == 0) {
        float raw = s_obs[N_VEH * DVEH + N_PED * DPED + lane];
        int a = (raw >= 0.5f) ? 1 : 0;
        unsigned m = __ballot_sync(0xffffffffu, a);
        int cnt = __popc(m);
        if (cnt == 0) { a = 1; cnt = NTOK; }
        s_alive[lane] = (float)a;
        s_bias[lane]  = a ? 0.f : -1e30f;
        if (lane == 0) s_inv = 1.0f / (float)cnt;
    }

    // ---- token embeddings via tf32 MMA -> bufP (PL layout) ----
    {
        const int n0w = warp * 32;
        float accV[4][4], accP[4][4];
#pragma unroll
        for (int nt = 0; nt < 4; ++nt) {
            const int c = n0w + nt * 8 + 2 * tig;
            float2 b2 = *(const float2*)&bv[c];
            accV[nt][0] = b2.x; accV[nt][1] = b2.y;
            accV[nt][2] = b2.x; accV[nt][3] = b2.y;
            float2 p2 = *(const float2*)&bp[c];
            accP[nt][0] = p2.x; accP[nt][1] = p2.y;
            accP[nt][2] = p2.x; accP[nt][3] = p2.y;
        }
        // vehicle: 5 k-tiles across 3 quad-packs (kp2 even-only)
#pragma unroll
        for (int kp = 0; kp < 3; ++kp) {
            int k = kp * 16 + tig;
            uint32_t aE[4];
            aE[0] = f2tf32(s_obs[gID * DVEH + k]);
            aE[1] = f2tf32(s_obs[(gID + 8) * DVEH + k]);
            aE[2] = f2tf32(s_obs[gID * DVEH + k + 4]);
            aE[3] = f2tf32(s_obs[(gID + 8) * DVEH + k + 4]);
            uint32_t aO[4];
            if (kp < 2) {
                int k2 = k + 8;
                aO[0] = f2tf32(s_obs[gID * DVEH + k2]);
                aO[1] = f2tf32(s_obs[(gID + 8) * DVEH + k2]);
                aO[2] = f2tf32(s_obs[gID * DVEH + k2 + 4]);
                aO[3] = f2tf32(s_obs[(gID + 8) * DVEH + k2 + 4]);
            }
#pragma unroll
            for (int nt = 0; nt < 4; ++nt) {
                uint4 bw = g_wvp4[kp][n0w + nt * 8 + gID][tig];
                mma_tf32(accV[nt], aE, bw.x, bw.y);
                if (kp < 2) mma_tf32(accV[nt], aO, bw.z, bw.w);
            }
        }
        // pedestrian: 3 k-tiles across 2 quad-packs (kp1 even-only)
#pragma unroll
        for (int kp = 0; kp < 2; ++kp) {
            const int base = N_VEH * DVEH;
            int k = kp * 16 + tig;
            uint32_t aE[4];
            aE[0] = f2tf32(s_obs[base + gID * DPED + k]);
            aE[1] = f2tf32(s_obs[base + (gID + 8) * DPED + k]);
            aE[2] = f2tf32(s_obs[base + gID * DPED + k + 4]);
            aE[3] = f2tf32(s_obs[base + (gID + 8) * DPED + k + 4]);
            uint32_t aO[4];
            if (kp < 1) {
                int k2 = k + 8;
                aO[0] = f2tf32(s_obs[base + gID * DPED + k2]);
                aO[1] = f2tf32(s_obs[base + (gID + 8) * DPED + k2]);
                aO[2] = f2tf32(s_obs[base + gID * DPED + k2 + 4]);
                aO[3] = f2tf32(s_obs[base + (gID + 8) * DPED + k2 + 4]);
            }
#pragma unroll
            for (int nt = 0; nt < 4; ++nt) {
                uint4 bw = g_wpp4[kp][n0w + nt * 8 + gID][tig];
                mma_tf32(accP[nt], aE, bw.x, bw.y);
                if (kp < 1) mma_tf32(accP[nt], aO, bw.z, bw.w);
            }
        }
        __syncthreads();   // obs fully consumed before bufP writes alias nothing; keep order
#pragma unroll
        for (int nt = 0; nt < 4; ++nt) {
            const int c = n0w + nt * 8 + 2 * tig;
            bufP[plOff(gID,      c)]     = tf32r(accV[nt][0]);
            bufP[plOff(gID,      c + 1)] = tf32r(accV[nt][1]);
            bufP[plOff(gID + 8,  c)]     = tf32r(accV[nt][2]);
            bufP[plOff(gID + 8,  c + 1)] = tf32r(accV[nt][3]);
            bufP[plOff(16 + gID,     c)]     = tf32r(accP[nt][0]);
            bufP[plOff(16 + gID,     c + 1)] = tf32r(accP[nt][1]);
            bufP[plOff(16 + gID + 8, c)]     = tf32r(accP[nt][2]);
            bufP[plOff(16 + gID + 8, c + 1)] = tf32r(accP[nt][3]);
        }
    }
    __syncthreads();

    float* xb = bufP;   // current x (PL)
    float* hb = bufQ;   // h target (QL) / next x target

    // ---- two GAT layers ----
#pragma unroll
    for (int l = 0; l < 2; ++l) {
        // Phase A1: h = x @ w via tf32 MMA; quad-packed B (LDG.128).
        {
            const int n0w = warp * 32;
            float acc[2][4][4];
            float accA[2][4];
#pragma unroll
            for (int mt = 0; mt < 2; ++mt) {
#pragma unroll
                for (int nt = 0; nt < 4; ++nt)
#pragma unroll
                    for (int r = 0; r < 4; ++r) acc[mt][nt][r] = 0.f;
#pragma unroll
                for (int r = 0; r < 4; ++r) accA[mt][r] = 0.f;
            }

#pragma unroll 2
            for (int kp = 0; kp < 8; ++kp) {
                const int pE = 8 * kp + tig;       // even kt pair index
                const int pO = 8 * kp + 4 + tig;   // odd kt pair index
                uint32_t aE[2][4], aO[2][4];
#pragma unroll
                for (int mt = 0; mt < 2; ++mt) {
                    const int r0 = mt * 16 + gID;
                    float2 v0 = *(const float2*)&xb[(r0 << 7) + ((pE ^ sigr) << 1)];
                    float2 v1 = *(const float2*)&xb[((r0 + 8) << 7) + ((pE ^ (sigr ^ 2)) << 1)];
                    aE[mt][0] = __float_as_uint(v0.x);
                    aE[mt][1] = __float_as_uint(v1.x);
                    aE[mt][2] = __float_as_uint(v0.y);
                    aE[mt][3] = __float_as_uint(v1.y);
                    float2 w0v = *(const float2*)&xb[(r0 << 7) + ((pO ^ sigr) << 1)];
                    float2 w1v = *(const float2*)&xb[((r0 + 8) << 7) + ((pO ^ (sigr ^ 2)) << 1)];
                    aO[mt][0] = __float_as_uint(w0v.x);
                    aO[mt][1] = __float_as_uint(w1v.x);
                    aO[mt][2] = __float_as_uint(w0v.y);
                    aO[mt][3] = __float_as_uint(w1v.y);
                }
#pragma unroll
                for (int nt = 0; nt < 4; ++nt) {
                    const int n = n0w + nt * 8 + gID;
                    uint4 bw = g_wtp4[l][kp][n][tig];
                    mma_tf32(acc[0][nt], aE[0], bw.x, bw.y);
                    mma_tf32(acc[1][nt], aE[1], bw.x, bw.y);
                    mma_tf32(acc[0][nt], aO[0], bw.z, bw.w);
                    mma_tf32(acc[1][nt], aO[1], bw.z, bw.w);
                }
                if (warp == 0) {
                    uint4 bA = g_wtAp4[l][kp][gID][tig];
                    mma_tf32(accA[0], aE[0], bA.x, bA.y);
                    mma_tf32(accA[1], aE[1], bA.x, bA.y);
                    mma_tf32(accA[0], aO[0], bA.z, bA.w);
                    mma_tf32(accA[1], aO[1], bA.z, bA.w);
                }
            }
            // epilogue: h into QL (scalar stores)
#pragma unroll
            for (int mt = 0; mt < 2; ++mt)
#pragma unroll
                for (int nt = 0; nt < 4; ++nt) {
                    const int r = mt * 16 + gID;
                    const int c = n0w + nt * 8 + 2 * tig;
                    hb[qlOff(r,     c)]     = tf32r(acc[mt][nt][0]);
                    hb[qlOff(r,     c + 1)] = tf32r(acc[mt][nt][1]);
                    hb[qlOff(r + 8, c)]     = tf32r(acc[mt][nt][2]);
                    hb[qlOff(r + 8, c + 1)] = tf32r(acc[mt][nt][3]);
                }
            if (warp == 0) {
#pragma unroll
                for (int mt = 0; mt < 2; ++mt) {
                    const int r = mt * 16 + gID;
#pragma unroll
                    for (int q = 0; q < 4; ++q) {
                        int row = (q < 2) ? r : (r + 8);
                        int col = 2 * tig + (q & 1);
                        float v = accA[mt][q];
                        if (col < 4) s_as[row][col] = v;
                        else         s_adt[col - 4][row] = v;
                    }
                }
            }
        }
        __syncthreads();   // x consumed; attn may overwrite xb

        // Phase B: shuffle-free softmax. warp = head, lane = dst row i.
        {
            const int siga = ((lane & 3) << 2) | ((lane >> 2) & 3);
            float as_i = s_as[lane][warp];
            float e[32];
#pragma unroll
            for (int jj = 0; jj < 8; ++jj) {
                float4 ad4 = *(const float4*)&s_adt[warp][4 * jj];
                float4 b4  = *(const float4*)&s_bias[4 * jj];
                float v;
                v = as_i + ad4.x; e[4 * jj + 0] = ((v > 0.f) ? v : 0.2f * v) + b4.x;
                v = as_i + ad4.y; e[4 * jj + 1] = ((v > 0.f) ? v : 0.2f * v) + b4.y;
                v = as_i + ad4.z; e[4 * jj + 2] = ((v > 0.f) ? v : 0.2f * v) + b4.z;
                v = as_i + ad4.w; e[4 * jj + 3] = ((v > 0.f) ? v : 0.2f * v) + b4.w;
            }
            float m0 = e[0], m1 = e[1], m2 = e[2], m3 = e[3];
#pragma unroll
            for (int j = 4; j < 32; j += 4) {
                m0 = fmaxf(m0, e[j]);     m1 = fmaxf(m1, e[j + 1]);
                m2 = fmaxf(m2, e[j + 2]); m3 = fmaxf(m3, e[j + 3]);
            }
            float m = fmaxf(fmaxf(m0, m1), fmaxf(m2, m3));
            float s0 = 0.f, s1 = 0.f, s2 = 0.f, s3 = 0.f;
#pragma unroll
            for (int j = 0; j < 32; j += 4) {
                e[j]     = __expf(e[j] - m);     s0 += e[j];
                e[j + 1] = __expf(e[j + 1] - m); s1 += e[j + 1];
                e[j + 2] = __expf(e[j + 2] - m); s2 += e[j + 2];
                e[j + 3] = __expf(e[j + 3] - m); s3 += e[j + 3];
            }
            float inv = __fdividef(1.0f, (s0 + s1) + (s2 + s3));
#pragma unroll
            for (int p = 0; p < 16; ++p) {
                int j = ((p >> 2) << 3) | (p & 3);
                *(float2*)&xb[(warp << 10) + (lane << 5) + ((p ^ siga) << 1)] =
                    make_float2(tf32r(e[j] * inv), tf32r(e[j + 4] * inv));
            }
        }
        __syncthreads();

        // Phase C: out = attn_h @ h_h via tf32 MMA (A from AL, B from QL).
        {
            const int n0 = warp * 32;
            float acc[2][4][4];
#pragma unroll
            for (int mt = 0; mt < 2; ++mt)
#pragma unroll
                for (int nt = 0; nt < 4; ++nt)
#pragma unroll
                    for (int r = 0; r < 4; ++r) acc[mt][nt][r] = 0.f;

#pragma unroll
            for (int kt = 0; kt < 4; ++kt) {
                const int pC = kt * 4 + tig;
                uint32_t a[2][4];
#pragma unroll
                for (int mt = 0; mt < 2; ++mt) {
                    const int r0 = mt * 16 + gID;
                    float2 v0 = *(const float2*)&xb[(warp << 10) + (r0 << 5) + ((pC ^ sigr) << 1)];
                    float2 v1 = *(const float2*)&xb[(warp << 10) + ((r0 + 8) << 5) + ((pC ^ (sigr ^ 2)) << 1)];
                    a[mt][0] = __float_as_uint(v0.x);
                    a[mt][1] = __float_as_uint(v1.x);
                    a[mt][2] = __float_as_uint(v0.y);
                    a[mt][3] = __float_as_uint(v1.y);
                }
#pragma unroll
                for (int nt = 0; nt < 4; ++nt) {
                    const int n = n0 + nt * 8 + gID;
                    float2 bw = *(const float2*)&hb[(pC << 8) + ((n ^ (tig << 2)) << 1)];
                    mma_tf32(acc[0][nt], a[0], __float_as_uint(bw.x), __float_as_uint(bw.y));
                    mma_tf32(acc[1][nt], a[1], __float_as_uint(bw.x), __float_as_uint(bw.y));
                }
            }

            if (l == 0) {
                // order all B-frag reads (cross-warp ranges overlap) before overwrite
                __syncthreads();
#pragma unroll
                for (int mt = 0; mt < 2; ++mt)
#pragma unroll
                    for (int nt = 0; nt < 4; ++nt) {
                        const int r = mt * 16 + gID;
                        const int c = n0 + nt * 8 + 2 * tig;
                        float o0 = acc[mt][nt][0], o1 = acc[mt][nt][1];
                        float o2 = acc[mt][nt][2], o3 = acc[mt][nt][3];
                        o0 = (o0 > 0.f) ? o0 : (__expf(o0) - 1.0f);
                        o1 = (o1 > 0.f) ? o1 : (__expf(o1) - 1.0f);
                        o2 = (o2 > 0.f) ? o2 : (__expf(o2) - 1.0f);
                        o3 = (o3 > 0.f) ? o3 : (__expf(o3) - 1.0f);
                        hb[plOff(r,     c)]     = tf32r(o0);
                        hb[plOff(r,     c + 1)] = tf32r(o1);
                        hb[plOff(r + 8, c)]     = tf32r(o2);
                        hb[plOff(r + 8, c + 1)] = tf32r(o3);
                    }
                __syncthreads();
                // swap roles: new x is in hb
                float* tmp = xb; xb = hb; hb = tmp;
            } else {
                // Fused masked-mean pooling: ELU + alive weights in registers,
                // shfl-reduce over gID (rows), gID==0 lanes store.
                float a0 = s_alive[gID];
                float a1 = s_alive[gID + 8];
                float a2 = s_alive[16 + gID];
                float a3 = s_alive[24 + gID];
                float p0[4], p1[4];
#pragma unroll
                for (int nt = 0; nt < 4; ++nt) {
                    float e00 = acc[0][nt][0], e01 = acc[0][nt][1];
                    float e02 = acc[0][nt][2], e03 = acc[0][nt][3];
                    float e10 = acc[1][nt][0], e11 = acc[1][nt][1];
                    float e12 = acc[1][nt][2], e13 = acc[1][nt][3];
                    e00 = (e00 > 0.f) ? e00 : (__expf(e00) - 1.0f);
                    e01 = (e01 > 0.f) ? e01 : (__expf(e01) - 1.0f);
                    e02 = (e02 > 0.f) ? e02 : (__expf(e02) - 1.0f);
                    e03 = (e03 > 0.f) ? e03 : (__expf(e03) - 1.0f);
                    e10 = (e10 > 0.f) ? e10 : (__expf(e10) - 1.0f);
                    e11 = (e11 > 0.f) ? e11 : (__expf(e11) - 1.0f);
                    e12 = (e12 > 0.f) ? e12 : (__expf(e12) - 1.0f);
                    e13 = (e13 > 0.f) ? e13 : (__expf(e13) - 1.0f);
                    p0[nt] = fmaf(e00, a0, fmaf(e02, a1, fmaf(e10, a2, e12 * a3)));
                    p1[nt] = fmaf(e01, a0, fmaf(e03, a1, fmaf(e11, a2, e13 * a3)));
                }
#pragma unroll
                for (int off = 4; off <= 16; off <<= 1) {
#pragma unroll
                    for (int nt = 0; nt < 4; ++nt) {
                        p0[nt] += __shfl_xor_sync(0xffffffffu, p0[nt], off);
                        p1[nt] += __shfl_xor_sync(0xffffffffu, p1[nt], off);
                    }
                }
                if (gID == 0) {
                    float inv = s_inv;
#pragma unroll
                    for (int nt = 0; nt < 4; ++nt) {
                        const int c = n0 + nt * 8 + 2 * tig;
                        *(float2*)&out[(size_t)b * EDIM + c] =
                            make_float2(p0[nt] * inv, p1[nt] * inv);
                    }
                }
            }
        }
    }
}

extern "C" void kernel_launch(void* const* d_in, const int* in_sizes, int n_in,
                              void* d_out, int out_size) {
    const float* obs = (const float*)d_in[0];
    const float* Wv  = (const float*)d_in[1];
    const float* bv  = (const float*)d_in[2];
    const float* Wp  = (const float*)d_in[3];
    const float* bp  = (const float*)d_in[4];
    const float* w0  = (const float*)d_in[5];
    const float* as0 = (const float*)d_in[6];
    const float* ad0 = (const float*)d_in[7];
    const float* w1  = (const float*)d_in[8];
    const float* as1 = (const float*)d_in[9];
    const float* ad1 = (const float*)d_in[10];
    float* out = (float*)d_out;

    int B = in_sizes[0] / OBSD;

    size_t shmem = 8192 * sizeof(float);   // 32 KB
    cudaFuncSetAttribute(gnn_kernel, cudaFuncAttributeMaxDynamicSharedMemorySize, (int)shmem);

    int prep_total = 8192 + 512 + 1536 + 1024;   // 11264
    prep_kernel<<<(prep_total + 255) / 256, 256>>>(w0, as0, ad0, w1, as1, ad1, Wv, Wp);
    gnn_kernel<<<B, 128, shmem>>>(obs, bv, bp, out);
}

// round 13
// speedup vs baseline: 1.1164x; 1.1164x over previous
#include <cuda_runtime.h>
#include <cstdint>

#define N_VEH 16
#define N_PED 16
#define NTOK  32
#define DVEH  40
#define DPED  24
#define EDIM  128
#define NHEAD 4
#define OBSD  1056   // 16*40 + 16*24 + 32

// Packed tf32 weights: g_wtp[l][kt][n][tig] = (w[kt*8+tig][n], w[kt*8+tig+4][n])
__device__ uint2 g_wtp[2][16][EDIM][4];
// Packed folded-alpha weights: [l][kt][j][tig], j: 0-3 src head j, 4-7 dst head j-4
__device__ uint2 g_wtAp[2][16][8][4];
// Packed embedding weights (tf32 pairs): Wv 5 k-tiles, Wp 3 k-tiles.
__device__ uint2 g_wvp[5][EDIM][4];
__device__ uint2 g_wpp[3][EDIM][4];

__device__ __forceinline__ uint32_t f2tf32(float f) {
    uint32_t r;
    asm("cvt.rna.tf32.f32 %0, %1;" : "=r"(r) : "f"(f));
    return r;
}
__device__ __forceinline__ float tf32r(float f) {
    return __uint_as_float(f2tf32(f));
}

__device__ __forceinline__ void mma_tf32(float* c, const uint32_t* a,
                                         uint32_t b0, uint32_t b1) {
    asm("mma.sync.aligned.m16n8k8.row.col.f32.tf32.tf32.f32 "
        "{%0,%1,%2,%3}, {%4,%5,%6,%7}, {%8,%9}, {%0,%1,%2,%3};"
        : "+f"(c[0]), "+f"(c[1]), "+f"(c[2]), "+f"(c[3])
        : "r"(a[0]), "r"(a[1]), "r"(a[2]), "r"(a[3]), "r"(b0), "r"(b1));
}

// ---- fragment-paired SMEM layouts ----
// PL (x matrices): pair (r, c) with (r, c+4) adjacent; bank-XOR on pair index.
__device__ __forceinline__ int plOff(int r, int c) {
    int p   = ((c >> 3) << 2) | (c & 3);     // pair index 0..63
    int hi  = (c >> 2) & 1;
    int sig = ((r & 3) << 2) | ((r >> 2) & 3);
    return (r << 7) + (((p ^ sig)) << 1) + hi;
}
// QL (h matrices): pair (r, c) with (r+4, c) adjacent.
__device__ __forceinline__ int qlOff(int r, int c) {
    int rr = ((r >> 3) << 2) | (r & 3);      // row-pair index 0..15
    int hi = (r >> 2) & 1;
    return (rr << 8) + ((c ^ ((rr & 3) << 2)) << 1) + hi;
}

// Fused prep: pack main, alpha, and embedding weights as tf32 uint2 pairs.
__global__ void prep_kernel(const float* __restrict__ w0,
                            const float* __restrict__ as0, const float* __restrict__ ad0,
                            const float* __restrict__ w1,
                            const float* __restrict__ as1, const float* __restrict__ ad1,
                            const float* __restrict__ Wv, const float* __restrict__ Wp) {
    int idx = blockIdx.x * blockDim.x + threadIdx.x;
    if (idx < 16384) {                       // main weights: 2*16*128*4
        int l   = idx >> 13;
        int rem = idx & 8191;
        int kt  = rem >> 9;
        int n   = (rem >> 2) & 127;
        int tig = rem & 3;
        const float* w = l ? w1 : w0;
        g_wtp[l][kt][n][tig] =
            make_uint2(f2tf32(w[(kt * 8 + tig) * EDIM + n]),
                       f2tf32(w[(kt * 8 + tig + 4) * EDIM + n]));
    } else if (idx < 16384 + 1024) {         // folded alpha: 2*16*8*4
        int i2  = idx - 16384;
        int l   = i2 >> 9;
        int kt  = (i2 >> 5) & 15;
        int j   = (i2 >> 2) & 7;
        int tig = i2 & 3;
        const float* w = l ? w1 : w0;
        int h = j & 3;
        const float* a = (j < 4) ? (l ? as1 : as0) : (l ? ad1 : ad0);
        float s0 = 0.f, s1 = 0.f;
#pragma unroll
        for (int d = 0; d < 32; ++d) {
            float av = a[h * 32 + d];
            s0 = fmaf(w[(kt * 8 + tig) * EDIM + h * 32 + d],     av, s0);
            s1 = fmaf(w[(kt * 8 + tig + 4) * EDIM + h * 32 + d], av, s1);
        }
        g_wtAp[l][kt][j][tig] = make_uint2(f2tf32(s0), f2tf32(s1));
    } else if (idx < 16384 + 1024 + 2560) {  // Wv: 5*128*4
        int i2  = idx - 16384 - 1024;
        int kt  = i2 >> 9;
        int n   = (i2 >> 2) & 127;
        int tig = i2 & 3;
        g_wvp[kt][n][tig] =
            make_uint2(f2tf32(Wv[(kt * 8 + tig) * EDIM + n]),
                       f2tf32(Wv[(kt * 8 + tig + 4) * EDIM + n]));
    } else if (idx < 16384 + 1024 + 2560 + 1536) {   // Wp: 3*128*4
        int i2  = idx - 16384 - 1024 - 2560;
        int kt  = i2 >> 9;
        int n   = (i2 >> 2) & 127;
        int tig = i2 & 3;
        g_wpp[kt][n][tig] =
            make_uint2(f2tf32(Wp[(kt * 8 + tig) * EDIM + n]),
                       f2tf32(Wp[(kt * 8 + tig + 4) * EDIM + n]));
    }
}

__global__ __launch_bounds__(128, 6) void gnn_kernel(
    const float* __restrict__ obs,
    const float* __restrict__ bv, const float* __restrict__ bp,
    float* __restrict__ out)
{
    const int b    = blockIdx.x;
    const int t    = threadIdx.x;
    const int lane = t & 31;
    const int warp = t >> 5;
    const int gID  = lane >> 2;
    const int tig  = lane & 3;
    const int sigr = ((gID & 3) << 2) | (gID >> 2);

    extern __shared__ float smem[];
    float* bufP = smem;
    float* bufQ = smem + 4096;

    __shared__ float s_as[NTOK][NHEAD];
    __shared__ float s_adt[NHEAD][NTOK];
    __shared__ float s_bias[NTOK];
    __shared__ float s_alive[NTOK];
    __shared__ float s_inv;

    // ---- stage observation row into bufQ ----
    {
        const float4* src = (const float4*)(obs + (size_t)b * OBSD);
        float4* dst = (float4*)bufQ;
        for (int i = t; i < OBSD / 4; i += 128) dst[i] = src[i];
    }
    __syncthreads();
    const float* s_obs = bufQ;

    // ---- alive mask (warp 0) ----
    if (warp == 0) {
        float raw = s_obs[N_VEH * DVEH + N_PED * DPED + lane];
        int a = (raw >= 0.5f) ? 1 : 0;
        unsigned m = __ballot_sync(0xffffffffu, a);
        int cnt = __popc(m);
        if (cnt == 0) { a = 1; cnt = NTOK; }
        s_alive[lane] = (float)a;
        s_bias[lane]  = a ? 0.f : -1e30f;
        if (lane == 0) s_inv = 1.0f / (float)cnt;
    }

    // ---- token embeddings via tf32 MMA -> bufP (PL layout) ----
    // veh tile: rows 0-15 (tokens), ped tile: rows 16-31. Bias in acc init.
    {
        const int n0w = warp * 32;
        float accV[4][4], accP[4][4];
#pragma unroll
        for (int nt = 0; nt < 4; ++nt) {
            const int c = n0w + nt * 8 + 2 * tig;
            float2 b2 = *(const float2*)&bv[c];
            accV[nt][0] = b2.x; accV[nt][1] = b2.y;
            accV[nt][2] = b2.x; accV[nt][3] = b2.y;
            float2 p2 = *(const float2*)&bp[c];
            accP[nt][0] = p2.x; accP[nt][1] = p2.y;
            accP[nt][2] = p2.x; accP[nt][3] = p2.y;
        }
        // vehicle: k = 0..39, 5 k-tiles
#pragma unroll
        for (int kt = 0; kt < 5; ++kt) {
            const int k = kt * 8 + tig;
            uint32_t a[4];
            a[0] = f2tf32(s_obs[gID * DVEH + k]);
            a[1] = f2tf32(s_obs[(gID + 8) * DVEH + k]);
            a[2] = f2tf32(s_obs[gID * DVEH + k + 4]);
            a[3] = f2tf32(s_obs[(gID + 8) * DVEH + k + 4]);
#pragma unroll
            for (int nt = 0; nt < 4; ++nt) {
                uint2 bw = g_wvp[kt][n0w + nt * 8 + gID][tig];
                mma_tf32(accV[nt], a, bw.x, bw.y);
            }
        }
        // pedestrian: k = 0..23, 3 k-tiles, tokens 16-31
#pragma unroll
        for (int kt = 0; kt < 3; ++kt) {
            const int k = kt * 8 + tig;
            const int base = N_VEH * DVEH;
            uint32_t a[4];
            a[0] = f2tf32(s_obs[base + gID * DPED + k]);
            a[1] = f2tf32(s_obs[base + (gID + 8) * DPED + k]);
            a[2] = f2tf32(s_obs[base + gID * DPED + k + 4]);
            a[3] = f2tf32(s_obs[base + (gID + 8) * DPED + k + 4]);
#pragma unroll
            for (int nt = 0; nt < 4; ++nt) {
                uint2 bw = g_wpp[kt][n0w + nt * 8 + gID][tig];
                mma_tf32(accP[nt], a, bw.x, bw.y);
            }
        }
        // epilogue: write x into bufP (PL), tf32-rounded
#pragma unroll
        for (int nt = 0; nt < 4; ++nt) {
            const int c = n0w + nt * 8 + 2 * tig;
            bufP[plOff(gID,      c)]     = tf32r(accV[nt][0]);
            bufP[plOff(gID,      c + 1)] = tf32r(accV[nt][1]);
            bufP[plOff(gID + 8,  c)]     = tf32r(accV[nt][2]);
            bufP[plOff(gID + 8,  c + 1)] = tf32r(accV[nt][3]);
            bufP[plOff(16 + gID,     c)]     = tf32r(accP[nt][0]);
            bufP[plOff(16 + gID,     c + 1)] = tf32r(accP[nt][1]);
            bufP[plOff(16 + gID + 8, c)]     = tf32r(accP[nt][2]);
            bufP[plOff(16 + gID + 8, c + 1)] = tf32r(accP[nt][3]);
        }
    }
    __syncthreads();

    float* xb = bufP;   // current x (PL)
    float* hb = bufQ;   // h target (QL) / next x target

    // ---- two GAT layers ----
#pragma unroll
    for (int l = 0; l < 2; ++l) {
        // Phase A1: h = x @ w via tf32 MMA (A from PL via LDS.64, B packed LDG.64).
        {
            const int n0w = warp * 32;
            float acc[2][4][4];
            float accA[2][4];
#pragma unroll
            for (int mt = 0; mt < 2; ++mt) {
#pragma unroll
                for (int nt = 0; nt < 4; ++nt)
#pragma unroll
                    for (int r = 0; r < 4; ++r) acc[mt][nt][r] = 0.f;
#pragma unroll
                for (int r = 0; r < 4; ++r) accA[mt][r] = 0.f;
            }

#pragma unroll 4
            for (int kt = 0; kt < 16; ++kt) {
                const int pA = kt * 4 + tig;
                uint32_t a[2][4];
#pragma unroll
                for (int mt = 0; mt < 2; ++mt) {
                    const int r0 = mt * 16 + gID;
                    float2 v0 = *(const float2*)&xb[(r0 << 7) + ((pA ^ sigr) << 1)];
                    float2 v1 = *(const float2*)&xb[((r0 + 8) << 7) + ((pA ^ (sigr ^ 2)) << 1)];
                    a[mt][0] = __float_as_uint(v0.x);
                    a[mt][1] = __float_as_uint(v1.x);
                    a[mt][2] = __float_as_uint(v0.y);
                    a[mt][3] = __float_as_uint(v1.y);
                }
#pragma unroll
                for (int nt = 0; nt < 4; ++nt) {
                    const int n = n0w + nt * 8 + gID;
                    uint2 bw = g_wtp[l][kt][n][tig];
                    mma_tf32(acc[0][nt], a[0], bw.x, bw.y);
                    mma_tf32(acc[1][nt], a[1], bw.x, bw.y);
                }
                if (warp == 0) {
                    uint2 bA = g_wtAp[l][kt][gID][tig];
                    mma_tf32(accA[0], a[0], bA.x, bA.y);
                    mma_tf32(accA[1], a[1], bA.x, bA.y);
                }
            }
            // epilogue: h into QL (scalar stores)
#pragma unroll
            for (int mt = 0; mt < 2; ++mt)
#pragma unroll
                for (int nt = 0; nt < 4; ++nt) {
                    const int r = mt * 16 + gID;
                    const int c = n0w + nt * 8 + 2 * tig;
                    hb[qlOff(r,     c)]     = tf32r(acc[mt][nt][0]);
                    hb[qlOff(r,     c + 1)] = tf32r(acc[mt][nt][1]);
                    hb[qlOff(r + 8, c)]     = tf32r(acc[mt][nt][2]);
                    hb[qlOff(r + 8, c + 1)] = tf32r(acc[mt][nt][3]);
                }
            if (warp == 0) {
#pragma unroll
                for (int mt = 0; mt < 2; ++mt) {
                    const int r = mt * 16 + gID;
#pragma unroll
                    for (int q = 0; q < 4; ++q) {
                        int row = (q < 2) ? r : (r + 8);
                        int col = 2 * tig + (q & 1);
                        float v = accA[mt][q];
                        if (col < 4) s_as[row][col] = v;
                        else         s_adt[col - 4][row] = v;
                    }
                }
            }
        }
        __syncthreads();   // x consumed; attn may overwrite xb

        // Phase B: shuffle-free softmax. warp = head, lane = dst row i.
        {
            const int siga = ((lane & 3) << 2) | ((lane >> 2) & 3);
            float as_i = s_as[lane][warp];
            float e[32];
#pragma unroll
            for (int jj = 0; jj < 8; ++jj) {
                float4 ad4 = *(const float4*)&s_adt[warp][4 * jj];
                float4 b4  = *(const float4*)&s_bias[4 * jj];
                float v;
                v = as_i + ad4.x; e[4 * jj + 0] = ((v > 0.f) ? v : 0.2f * v) + b4.x;
                v = as_i + ad4.y; e[4 * jj + 1] = ((v > 0.f) ? v : 0.2f * v) + b4.y;
                v = as_i + ad4.z; e[4 * jj + 2] = ((v > 0.f) ? v : 0.2f * v) + b4.z;
                v = as_i + ad4.w; e[4 * jj + 3] = ((v > 0.f) ? v : 0.2f * v) + b4.w;
            }
            float m0 = e[0], m1 = e[1], m2 = e[2], m3 = e[3];
#pragma unroll
            for (int j = 4; j < 32; j += 4) {
                m0 = fmaxf(m0, e[j]);     m1 = fmaxf(m1, e[j + 1]);
                m2 = fmaxf(m2, e[j + 2]); m3 = fmaxf(m3, e[j + 3]);
            }
            float m = fmaxf(fmaxf(m0, m1), fmaxf(m2, m3));
            float s0 = 0.f, s1 = 0.f, s2 = 0.f, s3 = 0.f;
#pragma unroll
            for (int j = 0; j < 32; j += 4) {
                e[j]     = __expf(e[j] - m);     s0 += e[j];
                e[j + 1] = __expf(e[j + 1] - m); s1 += e[j + 1];
                e[j + 2] = __expf(e[j + 2] - m); s2 += e[j + 2];
                e[j + 3] = __expf(e[j + 3] - m); s3 += e[j + 3];
            }
            float inv = __fdividef(1.0f, (s0 + s1) + (s2 + s3));
            // write AL pairs (j, j+4) as STS.64
#pragma unroll
            for (int p = 0; p < 16; ++p) {
                int j = ((p >> 2) << 3) | (p & 3);
                *(float2*)&xb[(warp << 10) + (lane << 5) + ((p ^ siga) << 1)] =
                    make_float2(tf32r(e[j] * inv), tf32r(e[j + 4] * inv));
            }
        }
        __syncthreads();

        // Phase C: out = attn_h @ h_h via tf32 MMA (A from AL, B from QL, all LDS.64).
        {
            const int n0 = warp * 32;
            float acc[2][4][4];
#pragma unroll
            for (int mt = 0; mt < 2; ++mt)
#pragma unroll
                for (int nt = 0; nt < 4; ++nt)
#pragma unroll
                    for (int r = 0; r < 4; ++r) acc[mt][nt][r] = 0.f;

#pragma unroll
            for (int kt = 0; kt < 4; ++kt) {
                const int pC = kt * 4 + tig;
                uint32_t a[2][4];
#pragma unroll
                for (int mt = 0; mt < 2; ++mt) {
                    const int r0 = mt * 16 + gID;
                    float2 v0 = *(const float2*)&xb[(warp << 10) + (r0 << 5) + ((pC ^ sigr) << 1)];
                    float2 v1 = *(const float2*)&xb[(warp << 10) + ((r0 + 8) << 5) + ((pC ^ (sigr ^ 2)) << 1)];
                    a[mt][0] = __float_as_uint(v0.x);
                    a[mt][1] = __float_as_uint(v1.x);
                    a[mt][2] = __float_as_uint(v0.y);
                    a[mt][3] = __float_as_uint(v1.y);
                }
#pragma unroll
                for (int nt = 0; nt < 4; ++nt) {
                    const int n = n0 + nt * 8 + gID;
                    float2 bw = *(const float2*)&hb[(pC << 8) + ((n ^ (tig << 2)) << 1)];
                    mma_tf32(acc[0][nt], a[0], __float_as_uint(bw.x), __float_as_uint(bw.y));
                    mma_tf32(acc[1][nt], a[1], __float_as_uint(bw.x), __float_as_uint(bw.y));
                }
            }
            __syncwarp();

            if (l == 0) {
                // epilogue: ELU, write x' into hb in PL layout (round-10 ordering)
#pragma unroll
                for (int mt = 0; mt < 2; ++mt)
#pragma unroll
                    for (int nt = 0; nt < 4; ++nt) {
                        const int r = mt * 16 + gID;
                        const int c = n0 + nt * 8 + 2 * tig;
                        float o0 = acc[mt][nt][0], o1 = acc[mt][nt][1];
                        float o2 = acc[mt][nt][2], o3 = acc[mt][nt][3];
                        o0 = (o0 > 0.f) ? o0 : (__expf(o0) - 1.0f);
                        o1 = (o1 > 0.f) ? o1 : (__expf(o1) - 1.0f);
                        o2 = (o2 > 0.f) ? o2 : (__expf(o2) - 1.0f);
                        o3 = (o3 > 0.f) ? o3 : (__expf(o3) - 1.0f);
                        hb[plOff(r,     c)]     = tf32r(o0);
                        hb[plOff(r,     c + 1)] = tf32r(o1);
                        hb[plOff(r + 8, c)]     = tf32r(o2);
                        hb[plOff(r + 8, c + 1)] = tf32r(o3);
                    }
                __syncthreads();
                // swap roles: new x is in hb
                float* tmp = xb; xb = hb; hb = tmp;
            } else {
                // Fused masked-mean pooling: ELU + alive weights in registers,
                // shfl-reduce over gID (rows), gID==0 lanes store.
                float a0 = s_alive[gID];
                float a1 = s_alive[gID + 8];
                float a2 = s_alive[16 + gID];
                float a3 = s_alive[24 + gID];
                float p0[4], p1[4];
#pragma unroll
                for (int nt = 0; nt < 4; ++nt) {
                    float e00 = acc[0][nt][0], e01 = acc[0][nt][1];
                    float e02 = acc[0][nt][2], e03 = acc[0][nt][3];
                    float e10 = acc[1][nt][0], e11 = acc[1][nt][1];
                    float e12 = acc[1][nt][2], e13 = acc[1][nt][3];
                    e00 = (e00 > 0.f) ? e00 : (__expf(e00) - 1.0f);
                    e01 = (e01 > 0.f) ? e01 : (__expf(e01) - 1.0f);
                    e02 = (e02 > 0.f) ? e02 : (__expf(e02) - 1.0f);
                    e03 = (e03 > 0.f) ? e03 : (__expf(e03) - 1.0f);
                    e10 = (e10 > 0.f) ? e10 : (__expf(e10) - 1.0f);
                    e11 = (e11 > 0.f) ? e11 : (__expf(e11) - 1.0f);
                    e12 = (e12 > 0.f) ? e12 : (__expf(e12) - 1.0f);
                    e13 = (e13 > 0.f) ? e13 : (__expf(e13) - 1.0f);
                    p0[nt] = fmaf(e00, a0, fmaf(e02, a1, fmaf(e10, a2, e12 * a3)));
                    p1[nt] = fmaf(e01, a0, fmaf(e03, a1, fmaf(e11, a2, e13 * a3)));
                }
#pragma unroll
                for (int off = 4; off <= 16; off <<= 1) {
#pragma unroll
                    for (int nt = 0; nt < 4; ++nt) {
                        p0[nt] += __shfl_xor_sync(0xffffffffu, p0[nt], off);
                        p1[nt] += __shfl_xor_sync(0xffffffffu, p1[nt], off);
                    }
                }
                if (gID == 0) {
                    float inv = s_inv;
#pragma unroll
                    for (int nt = 0; nt < 4; ++nt) {
                        const int c = n0 + nt * 8 + 2 * tig;
                        *(float2*)&out[(size_t)b * EDIM + c] =
                            make_float2(p0[nt] * inv, p1[nt] * inv);
                    }
                }
            }
        }
    }
}

extern "C" void kernel_launch(void* const* d_in, const int* in_sizes, int n_in,
                              void* d_out, int out_size) {
    const float* obs = (const float*)d_in[0];
    const float* Wv  = (const float*)d_in[1];
    const float* bv  = (const float*)d_in[2];
    const float* Wp  = (const float*)d_in[3];
    const float* bp  = (const float*)d_in[4];
    const float* w0  = (const float*)d_in[5];
    const float* as0 = (const float*)d_in[6];
    const float* ad0 = (const float*)d_in[7];
    const float* w1  = (const float*)d_in[8];
    const float* as1 = (const float*)d_in[9];
    const float* ad1 = (const float*)d_in[10];
    float* out = (float*)d_out;

    int B = in_sizes[0] / OBSD;

    size_t shmem = 8192 * sizeof(float);   // 32 KB
    cudaFuncSetAttribute(gnn_kernel, cudaFuncAttributeMaxDynamicSharedMemorySize, (int)shmem);

    int prep_total = 16384 + 1024 + 2560 + 1536;   // 21504
    prep_kernel<<<(prep_total + 255) / 256, 256>>>(w0, as0, ad0, w1, as1, ad1, Wv, Wp);
    gnn_kernel<<<B, 128, shmem>>>(obs, bv, bp, out);
}

// round 14
// speedup vs baseline: 1.1245x; 1.0073x over previous
#include <cuda_runtime.h>
#include <cstdint>

#define N_VEH 16
#define N_PED 16
#define NTOK  32
#define DVEH  40
#define DPED  24
#define EDIM  128
#define NHEAD 4
#define OBSD  1056   // 16*40 + 16*24 + 32

// Packed tf32 weights: g_wtp[l][kt][n][tig] = (w[kt*8+tig][n], w[kt*8+tig+4][n])
__device__ uint2 g_wtp[2][16][EDIM][4];
// Packed folded-alpha weights: [l][kt][j][tig], j: 0-3 src head j, 4-7 dst head j-4
__device__ uint2 g_wtAp[2][16][8][4];
// Packed embedding weights (tf32 pairs): Wv 5 k-tiles, Wp 3 k-tiles.
__device__ uint2 g_wvp[5][EDIM][4];
__device__ uint2 g_wpp[3][EDIM][4];

__device__ __forceinline__ uint32_t f2tf32(float f) {
    uint32_t r;
    asm("cvt.rna.tf32.f32 %0, %1;" : "=r"(r) : "f"(f));
    return r;
}
__device__ __forceinline__ float tf32r(float f) {
    return __uint_as_float(f2tf32(f));
}

__device__ __forceinline__ void mma_tf32(float* c, const uint32_t* a,
                                         uint32_t b0, uint32_t b1) {
    asm("mma.sync.aligned.m16n8k8.row.col.f32.tf32.tf32.f32 "
        "{%0,%1,%2,%3}, {%4,%5,%6,%7}, {%8,%9}, {%0,%1,%2,%3};"
        : "+f"(c[0]), "+f"(c[1]), "+f"(c[2]), "+f"(c[3])
        : "r"(a[0]), "r"(a[1]), "r"(a[2]), "r"(a[3]), "r"(b0), "r"(b1));
}

// ---- fragment-paired SMEM layouts ----
// PL (x matrices): pair (r, c) with (r, c+4) adjacent; bank-XOR on pair index.
__device__ __forceinline__ int plOff(int r, int c) {
    int p   = ((c >> 3) << 2) | (c & 3);     // pair index 0..63
    int hi  = (c >> 2) & 1;
    int sig = ((r & 3) << 2) | ((r >> 2) & 3);
    return (r << 7) + (((p ^ sig)) << 1) + hi;
}
// QL (h matrices): pair (r, c) with (r+4, c) adjacent.
__device__ __forceinline__ int qlOff(int r, int c) {
    int rr = ((r >> 3) << 2) | (r & 3);      // row-pair index 0..15
    int hi = (r >> 2) & 1;
    return (rr << 8) + ((c ^ ((rr & 3) << 2)) << 1) + hi;
}

// Fused prep: pack main, alpha, and embedding weights as tf32 uint2 pairs.
__global__ void prep_kernel(const float* __restrict__ w0,
                            const float* __restrict__ as0, const float* __restrict__ ad0,
                            const float* __restrict__ w1,
                            const float* __restrict__ as1, const float* __restrict__ ad1,
                            const float* __restrict__ Wv, const float* __restrict__ Wp) {
    int idx = blockIdx.x * blockDim.x + threadIdx.x;
    if (idx < 16384) {                       // main weights: 2*16*128*4
        int l   = idx >> 13;
        int rem = idx & 8191;
        int kt  = rem >> 9;
        int n   = (rem >> 2) & 127;
        int tig = rem & 3;
        const float* w = l ? w1 : w0;
        g_wtp[l][kt][n][tig] =
            make_uint2(f2tf32(w[(kt * 8 + tig) * EDIM + n]),
                       f2tf32(w[(kt * 8 + tig + 4) * EDIM + n]));
    } else if (idx < 16384 + 1024) {         // folded alpha: 2*16*8*4
        int i2  = idx - 16384;
        int l   = i2 >> 9;
        int kt  = (i2 >> 5) & 15;
        int j   = (i2 >> 2) & 7;
        int tig = i2 & 3;
        const float* w = l ? w1 : w0;
        int h = j & 3;
        const float* a = (j < 4) ? (l ? as1 : as0) : (l ? ad1 : ad0);
        float s0 = 0.f, s1 = 0.f;
#pragma unroll
        for (int d = 0; d < 32; ++d) {
            float av = a[h * 32 + d];
            s0 = fmaf(w[(kt * 8 + tig) * EDIM + h * 32 + d],     av, s0);
            s1 = fmaf(w[(kt * 8 + tig + 4) * EDIM + h * 32 + d], av, s1);
        }
        g_wtAp[l][kt][j][tig] = make_uint2(f2tf32(s0), f2tf32(s1));
    } else if (idx < 16384 + 1024 + 2560) {  // Wv: 5*128*4
        int i2  = idx - 16384 - 1024;
        int kt  = i2 >> 9;
        int n   = (i2 >> 2) & 127;
        int tig = i2 & 3;
        g_wvp[kt][n][tig] =
            make_uint2(f2tf32(Wv[(kt * 8 + tig) * EDIM + n]),
                       f2tf32(Wv[(kt * 8 + tig + 4) * EDIM + n]));
    } else if (idx < 16384 + 1024 + 2560 + 1536) {   // Wp: 3*128*4
        int i2  = idx - 16384 - 1024 - 2560;
        int kt  = i2 >> 9;
        int n   = (i2 >> 2) & 127;
        int tig = i2 & 3;
        g_wpp[kt][n][tig] =
            make_uint2(f2tf32(Wp[(kt * 8 + tig) * EDIM + n]),
                       f2tf32(Wp[(kt * 8 + tig + 4) * EDIM + n]));
    }
}

__global__ __launch_bounds__(128, 6) void gnn_kernel(
    const float* __restrict__ obs,
    const float* __restrict__ bv, const float* __restrict__ bp,
    float* __restrict__ out)
{
    const int b    = blockIdx.x;
    const int t    = threadIdx.x;
    const int lane = t & 31;
    const int warp = t >> 5;
    const int gID  = lane >> 2;
    const int tig  = lane & 3;
    const int sigr = ((gID & 3) << 2) | (gID >> 2);

    extern __shared__ float smem[];
    float* xb = smem;          // x buffer (PL) — never clobbered by attn
    float* hb = smem + 4096;   // h buffer (QL) / obs staging

    __shared__ float s_as[NTOK][NHEAD];
    __shared__ float s_adt[NHEAD][NTOK];
    __shared__ float s_bias[NTOK];
    __shared__ float s_alive[NTOK];
    __shared__ float s_inv;

    // ---- stage observation row into hb ----
    {
        const float4* src = (const float4*)(obs + (size_t)b * OBSD);
        float4* dst = (float4*)hb;
        for (int i = t; i < OBSD / 4; i += 128) dst[i] = src[i];
    }
    __syncthreads();
    const float* s_obs = hb;

    // ---- alive mask (warp 0) ----
    if (warp == 0) {
        float raw = s_obs[N_VEH * DVEH + N_PED * DPED + lane];
        int a = (raw >= 0.5f) ? 1 : 0;
        unsigned m = __ballot_sync(0xffffffffu, a);
        int cnt = __popc(m);
        if (cnt == 0) { a = 1; cnt = NTOK; }
        s_alive[lane] = (float)a;
        s_bias[lane]  = a ? 0.f : -1e30f;
        if (lane == 0) s_inv = 1.0f / (float)cnt;
    }

    // ---- token embeddings via tf32 MMA -> xb (PL layout) ----
    {
        const int n0w = warp * 32;
        float accV[4][4], accP[4][4];
#pragma unroll
        for (int nt = 0; nt < 4; ++nt) {
            const int c = n0w + nt * 8 + 2 * tig;
            float2 b2 = *(const float2*)&bv[c];
            accV[nt][0] = b2.x; accV[nt][1] = b2.y;
            accV[nt][2] = b2.x; accV[nt][3] = b2.y;
            float2 p2 = *(const float2*)&bp[c];
            accP[nt][0] = p2.x; accP[nt][1] = p2.y;
            accP[nt][2] = p2.x; accP[nt][3] = p2.y;
        }
#pragma unroll
        for (int kt = 0; kt < 5; ++kt) {
            const int k = kt * 8 + tig;
            uint32_t a[4];
            a[0] = f2tf32(s_obs[gID * DVEH + k]);
            a[1] = f2tf32(s_obs[(gID + 8) * DVEH + k]);
            a[2] = f2tf32(s_obs[gID * DVEH + k + 4]);
            a[3] = f2tf32(s_obs[(gID + 8) * DVEH + k + 4]);
#pragma unroll
            for (int nt = 0; nt < 4; ++nt) {
                uint2 bw = g_wvp[kt][n0w + nt * 8 + gID][tig];
                mma_tf32(accV[nt], a, bw.x, bw.y);
            }
        }
#pragma unroll
        for (int kt = 0; kt < 3; ++kt) {
            const int k = kt * 8 + tig;
            const int base = N_VEH * DVEH;
            uint32_t a[4];
            a[0] = f2tf32(s_obs[base + gID * DPED + k]);
            a[1] = f2tf32(s_obs[base + (gID + 8) * DPED + k]);
            a[2] = f2tf32(s_obs[base + gID * DPED + k + 4]);
            a[3] = f2tf32(s_obs[base + (gID + 8) * DPED + k + 4]);
#pragma unroll
            for (int nt = 0; nt < 4; ++nt) {
                uint2 bw = g_wpp[kt][n0w + nt * 8 + gID][tig];
                mma_tf32(accP[nt], a, bw.x, bw.y);
            }
        }
        // epilogue: write x into xb (PL), tf32-rounded
#pragma unroll
        for (int nt = 0; nt < 4; ++nt) {
            const int c = n0w + nt * 8 + 2 * tig;
            xb[plOff(gID,      c)]     = tf32r(accV[nt][0]);
            xb[plOff(gID,      c + 1)] = tf32r(accV[nt][1]);
            xb[plOff(gID + 8,  c)]     = tf32r(accV[nt][2]);
            xb[plOff(gID + 8,  c + 1)] = tf32r(accV[nt][3]);
            xb[plOff(16 + gID,     c)]     = tf32r(accP[nt][0]);
            xb[plOff(16 + gID,     c + 1)] = tf32r(accP[nt][1]);
            xb[plOff(16 + gID + 8, c)]     = tf32r(accP[nt][2]);
            xb[plOff(16 + gID + 8, c + 1)] = tf32r(accP[nt][3]);
        }
    }
    __syncthreads();

    // ---- two GAT layers ----
#pragma unroll
    for (int l = 0; l < 2; ++l) {
        // Phase A1: h = x @ w via tf32 MMA (A from PL via LDS.64, B packed LDG.64).
        {
            const int n0w = warp * 32;
            float acc[2][4][4];
            float accA[2][4];
#pragma unroll
            for (int mt = 0; mt < 2; ++mt) {
#pragma unroll
                for (int nt = 0; nt < 4; ++nt)
#pragma unroll
                    for (int r = 0; r < 4; ++r) acc[mt][nt][r] = 0.f;
#pragma unroll
                for (int r = 0; r < 4; ++r) accA[mt][r] = 0.f;
            }

#pragma unroll 4
            for (int kt = 0; kt < 16; ++kt) {
                const int pA = kt * 4 + tig;
                uint32_t a[2][4];
#pragma unroll
                for (int mt = 0; mt < 2; ++mt) {
                    const int r0 = mt * 16 + gID;
                    float2 v0 = *(const float2*)&xb[(r0 << 7) + ((pA ^ sigr) << 1)];
                    float2 v1 = *(const float2*)&xb[((r0 + 8) << 7) + ((pA ^ (sigr ^ 2)) << 1)];
                    a[mt][0] = __float_as_uint(v0.x);
                    a[mt][1] = __float_as_uint(v1.x);
                    a[mt][2] = __float_as_uint(v0.y);
                    a[mt][3] = __float_as_uint(v1.y);
                }
#pragma unroll
                for (int nt = 0; nt < 4; ++nt) {
                    const int n = n0w + nt * 8 + gID;
                    uint2 bw = g_wtp[l][kt][n][tig];
                    mma_tf32(acc[0][nt], a[0], bw.x, bw.y);
                    mma_tf32(acc[1][nt], a[1], bw.x, bw.y);
                }
                if (warp == 0) {
                    uint2 bA = g_wtAp[l][kt][gID][tig];
                    mma_tf32(accA[0], a[0], bA.x, bA.y);
                    mma_tf32(accA[1], a[1], bA.x, bA.y);
                }
            }
            // epilogue: h into QL (scalar stores)
#pragma unroll
            for (int mt = 0; mt < 2; ++mt)
#pragma unroll
                for (int nt = 0; nt < 4; ++nt) {
                    const int r = mt * 16 + gID;
                    const int c = n0w + nt * 8 + 2 * tig;
                    hb[qlOff(r,     c)]     = tf32r(acc[mt][nt][0]);
                    hb[qlOff(r,     c + 1)] = tf32r(acc[mt][nt][1]);
                    hb[qlOff(r + 8, c)]     = tf32r(acc[mt][nt][2]);
                    hb[qlOff(r + 8, c + 1)] = tf32r(acc[mt][nt][3]);
                }
            if (warp == 0) {
#pragma unroll
                for (int mt = 0; mt < 2; ++mt) {
                    const int r = mt * 16 + gID;
#pragma unroll
                    for (int q = 0; q < 4; ++q) {
                        int row = (q < 2) ? r : (r + 8);
                        int col = 2 * tig + (q & 1);
                        float v = accA[mt][q];
                        if (col < 4) s_as[row][col] = v;
                        else         s_adt[col - 4][row] = v;
                    }
                }
            }
        }
        __syncthreads();   // h + alphas ready

        // Phase BC: fused softmax + aggregation. Attn stays in registers.
        // Thread owns rows {gID, gID+8, gID+16, gID+24} x cols {tig+4u}.
        {
            const int n0 = warp * 32;
            // alpha_src for the 4 owned rows (broadcast-friendly scalar LDS)
            float asr[4];
            asr[0] = s_as[gID][warp];
            asr[1] = s_as[gID + 8][warp];
            asr[2] = s_as[gID + 16][warp];
            asr[3] = s_as[gID + 24][warp];

            float p[4][8];
#pragma unroll
            for (int u = 0; u < 8; ++u) {
                const int col = tig + 4 * u;
                float ad = s_adt[warp][col];
                float bi = s_bias[col];
#pragma unroll
                for (int r = 0; r < 4; ++r) {
                    float v = asr[r] + ad;
                    p[r][u] = ((v > 0.f) ? v : 0.2f * v) + bi;
                }
            }
            // per-row max: local over 8 cols, then 4-lane butterfly over tig
            float inv[4];
#pragma unroll
            for (int r = 0; r < 4; ++r) {
                float m = p[r][0];
#pragma unroll
                for (int u = 1; u < 8; ++u) m = fmaxf(m, p[r][u]);
                m = fmaxf(m, __shfl_xor_sync(0xffffffffu, m, 1));
                m = fmaxf(m, __shfl_xor_sync(0xffffffffu, m, 2));
                float s = 0.f;
#pragma unroll
                for (int u = 0; u < 8; ++u) {
                    p[r][u] = __expf(p[r][u] - m);
                    s += p[r][u];
                }
                s += __shfl_xor_sync(0xffffffffu, s, 1);
                s += __shfl_xor_sync(0xffffffffu, s, 2);
                inv[r] = __fdividef(1.0f, s);
            }
            // normalize + tf32-round in registers (A-frags)
#pragma unroll
            for (int r = 0; r < 4; ++r)
#pragma unroll
                for (int u = 0; u < 8; ++u)
                    p[r][u] = tf32r(p[r][u] * inv[r]);

            float acc[2][4][4];
#pragma unroll
            for (int mt = 0; mt < 2; ++mt)
#pragma unroll
                for (int nt = 0; nt < 4; ++nt)
#pragma unroll
                    for (int r = 0; r < 4; ++r) acc[mt][nt][r] = 0.f;

#pragma unroll
            for (int kt = 0; kt < 4; ++kt) {
                const int pC = kt * 4 + tig;
                uint32_t a[2][4];
                a[0][0] = __float_as_uint(p[0][2 * kt]);
                a[0][1] = __float_as_uint(p[1][2 * kt]);
                a[0][2] = __float_as_uint(p[0][2 * kt + 1]);
                a[0][3] = __float_as_uint(p[1][2 * kt + 1]);
                a[1][0] = __float_as_uint(p[2][2 * kt]);
                a[1][1] = __float_as_uint(p[3][2 * kt]);
                a[1][2] = __float_as_uint(p[2][2 * kt + 1]);
                a[1][3] = __float_as_uint(p[3][2 * kt + 1]);
#pragma unroll
                for (int nt = 0; nt < 4; ++nt) {
                    const int n = n0 + nt * 8 + gID;
                    float2 bw = *(const float2*)&hb[(pC << 8) + ((n ^ (tig << 2)) << 1)];
                    mma_tf32(acc[0][nt], a[0], __float_as_uint(bw.x), __float_as_uint(bw.y));
                    mma_tf32(acc[1][nt], a[1], __float_as_uint(bw.x), __float_as_uint(bw.y));
                }
            }

            if (l == 0) {
                // ELU epilogue -> xb (x buffer is dead after A1; no race, no pre-sync)
#pragma unroll
                for (int mt = 0; mt < 2; ++mt)
#pragma unroll
                    for (int nt = 0; nt < 4; ++nt) {
                        const int r = mt * 16 + gID;
                        const int c = n0 + nt * 8 + 2 * tig;
                        float o0 = acc[mt][nt][0], o1 = acc[mt][nt][1];
                        float o2 = acc[mt][nt][2], o3 = acc[mt][nt][3];
                        o0 = (o0 > 0.f) ? o0 : (__expf(o0) - 1.0f);
                        o1 = (o1 > 0.f) ? o1 : (__expf(o1) - 1.0f);
                        o2 = (o2 > 0.f) ? o2 : (__expf(o2) - 1.0f);
                        o3 = (o3 > 0.f) ? o3 : (__expf(o3) - 1.0f);
                        xb[plOff(r,     c)]     = tf32r(o0);
                        xb[plOff(r,     c + 1)] = tf32r(o1);
                        xb[plOff(r + 8, c)]     = tf32r(o2);
                        xb[plOff(r + 8, c + 1)] = tf32r(o3);
                    }
                __syncthreads();   // x' visible (and hb reads done) before layer-1 A1
            } else {
                // Fused masked-mean pooling.
                float a0 = s_alive[gID];
                float a1 = s_alive[gID + 8];
                float a2 = s_alive[16 + gID];
                float a3 = s_alive[24 + gID];
                float p0[4], p1[4];
#pragma unroll
                for (int nt = 0; nt < 4; ++nt) {
                    float e00 = acc[0][nt][0], e01 = acc[0][nt][1];
                    float e02 = acc[0][nt][2], e03 = acc[0][nt][3];
                    float e10 = acc[1][nt][0], e11 = acc[1][nt][1];
                    float e12 = acc[1][nt][2], e13 = acc[1][nt][3];
                    e00 = (e00 > 0.f) ? e00 : (__expf(e00) - 1.0f);
                    e01 = (e01 > 0.f) ? e01 : (__expf(e01) - 1.0f);
                    e02 = (e02 > 0.f) ? e02 : (__expf(e02) - 1.0f);
                    e03 = (e03 > 0.f) ? e03 : (__expf(e03) - 1.0f);
                    e10 = (e10 > 0.f) ? e10 : (__expf(e10) - 1.0f);
                    e11 = (e11 > 0.f) ? e11 : (__expf(e11) - 1.0f);
                    e12 = (e12 > 0.f) ? e12 : (__expf(e12) - 1.0f);
                    e13 = (e13 > 0.f) ? e13 : (__expf(e13) - 1.0f);
                    p0[nt] = fmaf(e00, a0, fmaf(e02, a1, fmaf(e10, a2, e12 * a3)));
                    p1[nt] = fmaf(e01, a0, fmaf(e03, a1, fmaf(e11, a2, e13 * a3)));
                }
#pragma unroll
                for (int off = 4; off <= 16; off <<= 1) {
#pragma unroll
                    for (int nt = 0; nt < 4; ++nt) {
                        p0[nt] += __shfl_xor_sync(0xffffffffu, p0[nt], off);
                        p1[nt] += __shfl_xor_sync(0xffffffffu, p1[nt], off);
                    }
                }
                if (gID == 0) {
                    float invc = s_inv;
#pragma unroll
                    for (int nt = 0; nt < 4; ++nt) {
                        const int c = n0 + nt * 8 + 2 * tig;
                        *(float2*)&out[(size_t)b * EDIM + c] =
                            make_float2(p0[nt] * invc, p1[nt] * invc);
                    }
                }
            }
        }
    }
}

extern "C" void kernel_launch(void* const* d_in, const int* in_sizes, int n_in,
                              void* d_out, int out_size) {
    const float* obs = (const float*)d_in[0];
    const float* Wv  = (const float*)d_in[1];
    const float* bv  = (const float*)d_in[2];
    const float* Wp  = (const float*)d_in[3];
    const float* bp  = (const float*)d_in[4];
    const float* w0  = (const float*)d_in[5];
    const float* as0 = (const float*)d_in[6];
    const float* ad0 = (const float*)d_in[7];
    const float* w1  = (const float*)d_in[8];
    const float* as1 = (const float*)d_in[9];
    const float* ad1 = (const float*)d_in[10];
    float* out = (float*)d_out;

    int B = in_sizes[0] / OBSD;

    size_t shmem = 8192 * sizeof(float);   // 32 KB
    cudaFuncSetAttribute(gnn_kernel, cudaFuncAttributeMaxDynamicSharedMemorySize, (int)shmem);

    int prep_total = 16384 + 1024 + 2560 + 1536;   // 21504
    prep_kernel<<<(prep_total + 255) / 256, 256>>>(w0, as0, ad0, w1, as1, ad1, Wv, Wp);
    gnn_kernel<<<B, 128, shmem>>>(obs, bv, bp, out);
}

// round 15
// speedup vs baseline: 1.2318x; 1.0954x over previous
#include <cuda_runtime.h>
#include <cstdint>

#define N_VEH 16
#define N_PED 16
#define NTOK  32
#define DVEH  40
#define DPED  24
#define EDIM  128
#define NHEAD 4
#define OBSD  1056   // 16*40 + 16*24 + 32

// Packed tf32 weights: g_wtp[l][kt][n][tig] = (w[kt*8+tig][n], w[kt*8+tig+4][n])
__device__ uint2 g_wtp[2][16][EDIM][4];
// Packed folded-alpha weights: [l][kt][j][tig], j: 0-3 src head j, 4-7 dst head j-4
__device__ uint2 g_wtAp[2][16][8][4];
// Packed embedding weights (tf32 pairs): Wv 5 k-tiles, Wp 3 k-tiles.
__device__ uint2 g_wvp[5][EDIM][4];
__device__ uint2 g_wpp[3][EDIM][4];

__device__ __forceinline__ uint32_t f2tf32(float f) {
    uint32_t r;
    asm("cvt.rna.tf32.f32 %0, %1;" : "=r"(r) : "f"(f));
    return r;
}
__device__ __forceinline__ float tf32r(float f) {
    return __uint_as_float(f2tf32(f));
}

__device__ __forceinline__ void mma_tf32(float* c, const uint32_t* a,
                                         uint32_t b0, uint32_t b1) {
    asm("mma.sync.aligned.m16n8k8.row.col.f32.tf32.tf32.f32 "
        "{%0,%1,%2,%3}, {%4,%5,%6,%7}, {%8,%9}, {%0,%1,%2,%3};"
        : "+f"(c[0]), "+f"(c[1]), "+f"(c[2]), "+f"(c[3])
        : "r"(a[0]), "r"(a[1]), "r"(a[2]), "r"(a[3]), "r"(b0), "r"(b1));
}

// ---- fragment-paired SMEM layouts ----
// PL (x matrices): pair (r, c) with (r, c+4) adjacent; bank-XOR on pair index.
__device__ __forceinline__ int plOff(int r, int c) {
    int p   = ((c >> 3) << 2) | (c & 3);     // pair index 0..63
    int hi  = (c >> 2) & 1;
    int sig = ((r & 3) << 2) | ((r >> 2) & 3);
    return (r << 7) + (((p ^ sig)) << 1) + hi;
}
// QL (h matrices): pair (r, c) with (r+4, c) adjacent.
__device__ __forceinline__ int qlOff(int r, int c) {
    int rr = ((r >> 3) << 2) | (r & 3);      // row-pair index 0..15
    int hi = (r >> 2) & 1;
    return (rr << 8) + ((c ^ ((rr & 3) << 2)) << 1) + hi;
}

// Fused prep: pack main, alpha, and embedding weights as tf32 uint2 pairs.
__global__ void prep_kernel(const float* __restrict__ w0,
                            const float* __restrict__ as0, const float* __restrict__ ad0,
                            const float* __restrict__ w1,
                            const float* __restrict__ as1, const float* __restrict__ ad1,
                            const float* __restrict__ Wv, const float* __restrict__ Wp) {
    int idx = blockIdx.x * blockDim.x + threadIdx.x;
    if (idx < 16384) {                       // main weights: 2*16*128*4
        int l   = idx >> 13;
        int rem = idx & 8191;
        int kt  = rem >> 9;
        int n   = (rem >> 2) & 127;
        int tig = rem & 3;
        const float* w = l ? w1 : w0;
        g_wtp[l][kt][n][tig] =
            make_uint2(f2tf32(w[(kt * 8 + tig) * EDIM + n]),
                       f2tf32(w[(kt * 8 + tig + 4) * EDIM + n]));
    } else if (idx < 16384 + 1024) {         // folded alpha: 2*16*8*4
        int i2  = idx - 16384;
        int l   = i2 >> 9;
        int kt  = (i2 >> 5) & 15;
        int j   = (i2 >> 2) & 7;
        int tig = i2 & 3;
        const float* w = l ? w1 : w0;
        int h = j & 3;
        const float* a = (j < 4) ? (l ? as1 : as0) : (l ? ad1 : ad0);
        float s0 = 0.f, s1 = 0.f;
#pragma unroll
        for (int d = 0; d < 32; ++d) {
            float av = a[h * 32 + d];
            s0 = fmaf(w[(kt * 8 + tig) * EDIM + h * 32 + d],     av, s0);
            s1 = fmaf(w[(kt * 8 + tig + 4) * EDIM + h * 32 + d], av, s1);
        }
        g_wtAp[l][kt][j][tig] = make_uint2(f2tf32(s0), f2tf32(s1));
    } else if (idx < 16384 + 1024 + 2560) {  // Wv: 5*128*4
        int i2  = idx - 16384 - 1024;
        int kt  = i2 >> 9;
        int n   = (i2 >> 2) & 127;
        int tig = i2 & 3;
        g_wvp[kt][n][tig] =
            make_uint2(f2tf32(Wv[(kt * 8 + tig) * EDIM + n]),
                       f2tf32(Wv[(kt * 8 + tig + 4) * EDIM + n]));
    } else if (idx < 16384 + 1024 + 2560 + 1536) {   // Wp: 3*128*4
        int i2  = idx - 16384 - 1024 - 2560;
        int kt  = i2 >> 9;
        int n   = (i2 >> 2) & 127;
        int tig = i2 & 3;
        g_wpp[kt][n][tig] =
            make_uint2(f2tf32(Wp[(kt * 8 + tig) * EDIM + n]),
                       f2tf32(Wp[(kt * 8 + tig + 4) * EDIM + n]));
    }
}

__global__ __launch_bounds__(128, 6) void gnn_kernel(
    const float* __restrict__ obs,
    const float* __restrict__ bv, const float* __restrict__ bp,
    float* __restrict__ out)
{
    const int b    = blockIdx.x;
    const int t    = threadIdx.x;
    const int lane = t & 31;
    const int warp = t >> 5;
    const int gID  = lane >> 2;
    const int tig  = lane & 3;
    const int sigr = ((gID & 3) << 2) | (gID >> 2);

    extern __shared__ float smem[];
    float* xb = smem;          // x buffer (PL) — never clobbered by attn
    float* hb = smem + 4096;   // h buffer (QL, warp-private col slices) / obs staging

    __shared__ float s_bias[NTOK];
    __shared__ float s_alive[NTOK];
    __shared__ float s_inv;

    // ---- stage observation row into hb ----
    {
        const float4* src = (const float4*)(obs + (size_t)b * OBSD);
        float4* dst = (float4*)hb;
        for (int i = t; i < OBSD / 4; i += 128) dst[i] = src[i];
    }
    __syncthreads();
    const float* s_obs = hb;

    // ---- alive mask (warp 0) ----
    if (warp == 0) {
        float raw = s_obs[N_VEH * DVEH + N_PED * DPED + lane];
        int a = (raw >= 0.5f) ? 1 : 0;
        unsigned m = __ballot_sync(0xffffffffu, a);
        int cnt = __popc(m);
        if (cnt == 0) { a = 1; cnt = NTOK; }
        s_alive[lane] = (float)a;
        s_bias[lane]  = a ? 0.f : -1e30f;
        if (lane == 0) s_inv = 1.0f / (float)cnt;
    }

    // ---- token embeddings via tf32 MMA -> xb (PL layout) ----
    {
        const int n0w = warp * 32;
        float accV[4][4], accP[4][4];
#pragma unroll
        for (int nt = 0; nt < 4; ++nt) {
            const int c = n0w + nt * 8 + 2 * tig;
            float2 b2 = *(const float2*)&bv[c];
            accV[nt][0] = b2.x; accV[nt][1] = b2.y;
            accV[nt][2] = b2.x; accV[nt][3] = b2.y;
            float2 p2 = *(const float2*)&bp[c];
            accP[nt][0] = p2.x; accP[nt][1] = p2.y;
            accP[nt][2] = p2.x; accP[nt][3] = p2.y;
        }
#pragma unroll
        for (int kt = 0; kt < 5; ++kt) {
            const int k = kt * 8 + tig;
            uint32_t a[4];
            a[0] = f2tf32(s_obs[gID * DVEH + k]);
            a[1] = f2tf32(s_obs[(gID + 8) * DVEH + k]);
            a[2] = f2tf32(s_obs[gID * DVEH + k + 4]);
            a[3] = f2tf32(s_obs[(gID + 8) * DVEH + k + 4]);
#pragma unroll
            for (int nt = 0; nt < 4; ++nt) {
                uint2 bw = g_wvp[kt][n0w + nt * 8 + gID][tig];
                mma_tf32(accV[nt], a, bw.x, bw.y);
            }
        }
#pragma unroll
        for (int kt = 0; kt < 3; ++kt) {
            const int k = kt * 8 + tig;
            const int base = N_VEH * DVEH;
            uint32_t a[4];
            a[0] = f2tf32(s_obs[base + gID * DPED + k]);
            a[1] = f2tf32(s_obs[base + (gID + 8) * DPED + k]);
            a[2] = f2tf32(s_obs[base + gID * DPED + k + 4]);
            a[3] = f2tf32(s_obs[base + (gID + 8) * DPED + k + 4]);
#pragma unroll
            for (int nt = 0; nt < 4; ++nt) {
                uint2 bw = g_wpp[kt][n0w + nt * 8 + gID][tig];
                mma_tf32(accP[nt], a, bw.x, bw.y);
            }
        }
        // epilogue: write x into xb (PL), tf32-rounded
#pragma unroll
        for (int nt = 0; nt < 4; ++nt) {
            const int c = n0w + nt * 8 + 2 * tig;
            xb[plOff(gID,      c)]     = tf32r(accV[nt][0]);
            xb[plOff(gID,      c + 1)] = tf32r(accV[nt][1]);
            xb[plOff(gID + 8,  c)]     = tf32r(accV[nt][2]);
            xb[plOff(gID + 8,  c + 1)] = tf32r(accV[nt][3]);
            xb[plOff(16 + gID,     c)]     = tf32r(accP[nt][0]);
            xb[plOff(16 + gID,     c + 1)] = tf32r(accP[nt][1]);
            xb[plOff(16 + gID + 8, c)]     = tf32r(accP[nt][2]);
            xb[plOff(16 + gID + 8, c + 1)] = tf32r(accP[nt][3]);
        }
    }
    __syncthreads();   // x visible to all warps; obs reads done before h writes

    // ---- two GAT layers ----
#pragma unroll
    for (int l = 0; l < 2; ++l) {
        float accA[2][4];   // alpha tile fragment — computed by ALL warps (identical)

        // Phase A1: h = x @ w via tf32 MMA (A from PL via LDS.64, B packed LDG.64).
        {
            const int n0w = warp * 32;
            float acc[2][4][4];
#pragma unroll
            for (int mt = 0; mt < 2; ++mt) {
#pragma unroll
                for (int nt = 0; nt < 4; ++nt)
#pragma unroll
                    for (int r = 0; r < 4; ++r) acc[mt][nt][r] = 0.f;
#pragma unroll
                for (int r = 0; r < 4; ++r) accA[mt][r] = 0.f;
            }

#pragma unroll 4
            for (int kt = 0; kt < 16; ++kt) {
                const int pA = kt * 4 + tig;
                uint32_t a[2][4];
#pragma unroll
                for (int mt = 0; mt < 2; ++mt) {
                    const int r0 = mt * 16 + gID;
                    float2 v0 = *(const float2*)&xb[(r0 << 7) + ((pA ^ sigr) << 1)];
                    float2 v1 = *(const float2*)&xb[((r0 + 8) << 7) + ((pA ^ (sigr ^ 2)) << 1)];
                    a[mt][0] = __float_as_uint(v0.x);
                    a[mt][1] = __float_as_uint(v1.x);
                    a[mt][2] = __float_as_uint(v0.y);
                    a[mt][3] = __float_as_uint(v1.y);
                }
#pragma unroll
                for (int nt = 0; nt < 4; ++nt) {
                    const int n = n0w + nt * 8 + gID;
                    uint2 bw = g_wtp[l][kt][n][tig];
                    mma_tf32(acc[0][nt], a[0], bw.x, bw.y);
                    mma_tf32(acc[1][nt], a[1], bw.x, bw.y);
                }
                {   // alpha MMA in every warp (warp-invariant operands)
                    uint2 bA = g_wtAp[l][kt][gID][tig];
                    mma_tf32(accA[0], a[0], bA.x, bA.y);
                    mma_tf32(accA[1], a[1], bA.x, bA.y);
                }
            }
            // epilogue: h into QL (warp-private col slice)
#pragma unroll
            for (int mt = 0; mt < 2; ++mt)
#pragma unroll
                for (int nt = 0; nt < 4; ++nt) {
                    const int r = mt * 16 + gID;
                    const int c = n0w + nt * 8 + 2 * tig;
                    hb[qlOff(r,     c)]     = tf32r(acc[mt][nt][0]);
                    hb[qlOff(r,     c + 1)] = tf32r(acc[mt][nt][1]);
                    hb[qlOff(r + 8, c)]     = tf32r(acc[mt][nt][2]);
                    hb[qlOff(r + 8, c + 1)] = tf32r(acc[mt][nt][3]);
                }
        }
        __syncwarp();   // h slice is warp-private: warp-level visibility suffices

        // Phase BC: fused softmax + aggregation. Alphas arrive via shfl from accA.
        // Thread owns rows {gID+8r} x cols {tig+4u} of the attn matrix (head=warp).
        {
            const int n0 = warp * 32;
            float asr[4];
#pragma unroll
            for (int r = 0; r < 4; ++r)
                asr[r] = __shfl_sync(0xffffffffu,
                                     accA[r >> 1][(warp & 1) + 2 * (r & 1)],
                                     4 * gID + (warp >> 1));
            float adv[8];
#pragma unroll
            for (int u = 0; u < 8; ++u)
                adv[u] = __shfl_sync(0xffffffffu,
                                     accA[u >> 2][(warp & 1) + 2 * ((u >> 1) & 1)],
                                     4 * tig + 16 * (u & 1) + 2 + (warp >> 1));

            float p[4][8];
#pragma unroll
            for (int u = 0; u < 8; ++u) {
                float ad = adv[u];
                float bi = s_bias[tig + 4 * u];
#pragma unroll
                for (int r = 0; r < 4; ++r) {
                    float v = asr[r] + ad;
                    p[r][u] = ((v > 0.f) ? v : 0.2f * v) + bi;
                }
            }
            // per-row max + sum: local over 8 cols, 4-lane butterfly over tig
            float inv[4];
#pragma unroll
            for (int r = 0; r < 4; ++r) {
                float m = p[r][0];
#pragma unroll
                for (int u = 1; u < 8; ++u) m = fmaxf(m, p[r][u]);
                m = fmaxf(m, __shfl_xor_sync(0xffffffffu, m, 1));
                m = fmaxf(m, __shfl_xor_sync(0xffffffffu, m, 2));
                float s = 0.f;
#pragma unroll
                for (int u = 0; u < 8; ++u) {
                    p[r][u] = __expf(p[r][u] - m);
                    s += p[r][u];
                }
                s += __shfl_xor_sync(0xffffffffu, s, 1);
                s += __shfl_xor_sync(0xffffffffu, s, 2);
                inv[r] = __fdividef(1.0f, s);
            }
#pragma unroll
            for (int r = 0; r < 4; ++r)
#pragma unroll
                for (int u = 0; u < 8; ++u)
                    p[r][u] = tf32r(p[r][u] * inv[r]);

            float acc[2][4][4];
#pragma unroll
            for (int mt = 0; mt < 2; ++mt)
#pragma unroll
                for (int nt = 0; nt < 4; ++nt)
#pragma unroll
                    for (int r = 0; r < 4; ++r) acc[mt][nt][r] = 0.f;

#pragma unroll
            for (int kt = 0; kt < 4; ++kt) {
                const int pC = kt * 4 + tig;
                uint32_t a[2][4];
                a[0][0] = __float_as_uint(p[0][2 * kt]);
                a[0][1] = __float_as_uint(p[1][2 * kt]);
                a[0][2] = __float_as_uint(p[0][2 * kt + 1]);
                a[0][3] = __float_as_uint(p[1][2 * kt + 1]);
                a[1][0] = __float_as_uint(p[2][2 * kt]);
                a[1][1] = __float_as_uint(p[3][2 * kt]);
                a[1][2] = __float_as_uint(p[2][2 * kt + 1]);
                a[1][3] = __float_as_uint(p[3][2 * kt + 1]);
#pragma unroll
                for (int nt = 0; nt < 4; ++nt) {
                    const int n = n0 + nt * 8 + gID;
                    float2 bw = *(const float2*)&hb[(pC << 8) + ((n ^ (tig << 2)) << 1)];
                    mma_tf32(acc[0][nt], a[0], __float_as_uint(bw.x), __float_as_uint(bw.y));
                    mma_tf32(acc[1][nt], a[1], __float_as_uint(bw.x), __float_as_uint(bw.y));
                }
            }

            if (l == 0) {
                // ELU epilogue -> xb (warp-private cols; x dead after A1)
#pragma unroll
                for (int mt = 0; mt < 2; ++mt)
#pragma unroll
                    for (int nt = 0; nt < 4; ++nt) {
                        const int r = mt * 16 + gID;
                        const int c = n0 + nt * 8 + 2 * tig;
                        float o0 = acc[mt][nt][0], o1 = acc[mt][nt][1];
                        float o2 = acc[mt][nt][2], o3 = acc[mt][nt][3];
                        o0 = (o0 > 0.f) ? o0 : (__expf(o0) - 1.0f);
                        o1 = (o1 > 0.f) ? o1 : (__expf(o1) - 1.0f);
                        o2 = (o2 > 0.f) ? o2 : (__expf(o2) - 1.0f);
                        o3 = (o3 > 0.f) ? o3 : (__expf(o3) - 1.0f);
                        xb[plOff(r,     c)]     = tf32r(o0);
                        xb[plOff(r,     c + 1)] = tf32r(o1);
                        xb[plOff(r + 8, c)]     = tf32r(o2);
                        xb[plOff(r + 8, c + 1)] = tf32r(o3);
                    }
                __syncthreads();   // x' visible to all warps before layer-1 A1
            } else {
                // Fused masked-mean pooling.
                float a0 = s_alive[gID];
                float a1 = s_alive[gID + 8];
                float a2 = s_alive[16 + gID];
                float a3 = s_alive[24 + gID];
                float p0[4], p1[4];
#pragma unroll
                for (int nt = 0; nt < 4; ++nt) {
                    float e00 = acc[0][nt][0], e01 = acc[0][nt][1];
                    float e02 = acc[0][nt][2], e03 = acc[0][nt][3];
                    float e10 = acc[1][nt][0], e11 = acc[1][nt][1];
                    float e12 = acc[1][nt][2], e13 = acc[1][nt][3];
                    e00 = (e00 > 0.f) ? e00 : (__expf(e00) - 1.0f);
                    e01 = (e01 > 0.f) ? e01 : (__expf(e01) - 1.0f);
                    e02 = (e02 > 0.f) ? e02 : (__expf(e02) - 1.0f);
                    e03 = (e03 > 0.f) ? e03 : (__expf(e03) - 1.0f);
                    e10 = (e10 > 0.f) ? e10 : (__expf(e10) - 1.0f);
                    e11 = (e11 > 0.f) ? e11 : (__expf(e11) - 1.0f);
                    e12 = (e12 > 0.f) ? e12 : (__expf(e12) - 1.0f);
                    e13 = (e13 > 0.f) ? e13 : (__expf(e13) - 1.0f);
                    p0[nt] = fmaf(e00, a0, fmaf(e02, a1, fmaf(e10, a2, e12 * a3)));
                    p1[nt] = fmaf(e01, a0, fmaf(e03, a1, fmaf(e11, a2, e13 * a3)));
                }
#pragma unroll
                for (int off = 4; off <= 16; off <<= 1) {
#pragma unroll
                    for (int nt = 0; nt < 4; ++nt) {
                        p0[nt] += __shfl_xor_sync(0xffffffffu, p0[nt], off);
                        p1[nt] += __shfl_xor_sync(0xffffffffu, p1[nt], off);
                    }
                }
                if (gID == 0) {
                    float invc = s_inv;
#pragma unroll
                    for (int nt = 0; nt < 4; ++nt) {
                        const int c = n0 + nt * 8 + 2 * tig;
                        *(float2*)&out[(size_t)b * EDIM + c] =
                            make_float2(p0[nt] * invc, p1[nt] * invc);
                    }
                }
            }
        }
    }
}

extern "C" void kernel_launch(void* const* d_in, const int* in_sizes, int n_in,
                              void* d_out, int out_size) {
    const float* obs = (const float*)d_in[0];
    const float* Wv  = (const float*)d_in[1];
    const float* bv  = (const float*)d_in[2];
    const float* Wp  = (const float*)d_in[3];
    const float* bp  = (const float*)d_in[4];
    const float* w0  = (const float*)d_in[5];
    const float* as0 = (const float*)d_in[6];
    const float* ad0 = (const float*)d_in[7];
    const float* w1  = (const float*)d_in[8];
    const float* as1 = (const float*)d_in[9];
    const float* ad1 = (const float*)d_in[10];
    float* out = (float*)d_out;

    int B = in_sizes[0] / OBSD;

    size_t shmem = 8192 * sizeof(float);   // 32 KB
    cudaFuncSetAttribute(gnn_kernel, cudaFuncAttributeMaxDynamicSharedMemorySize, (int)shmem);

    int prep_total = 16384 + 1024 + 2560 + 1536;   // 21504
    prep_kernel<<<(prep_total + 255) / 256, 256>>>(w0, as0, ad0, w1, as1, ad1, Wv, Wp);
    gnn_kernel<<<B, 128, shmem>>>(obs, bv, bp, out);
}